// round 4
// baseline (speedup 1.0000x reference)
#include <cuda_runtime.h>
#include <cstdint>

typedef unsigned long long ull;

// ---------------- problem constants (match setup_inputs) ----------------
#define NMAX 200000
#define DDIM 128
#define ADIM 64
#define RMAX 80
#define BMAX 256

// ---------------- device scratch (no allocs allowed) ----------------
// Lifetime-overlapped pool:
//   phase A (edge):   agg   = pool[0 : 128N]
//   phase B (W_h):    hnew  = pool[384N : 512N]   (reads agg, writes hnew)
//   phase C (W_ih):   gi    = pool[0 : 384N]      (reads hnew, overwrites dead agg)
//   phase D (gate):   reads gi
__device__ float g_pool[(size_t)NMAX * 512];
__device__ float g_hs_proj[NMAX * ADIM];      // hidden @ Ws^T          [N,64]
__device__ float g_relproj[RMAX * ADIM];      // rel_emb @ Wr^T         [R,64]
__device__ float g_qrproj[BMAX * ADIM];       // rel_emb[q_rel] @ Wqr^T + b_qr  [B,64]

#define G_AGG  (g_pool)
#define G_HNEW (g_pool + (size_t)NMAX * 384)
#define G_GI   (g_pool)

// ---------------- f32x2 helpers (packed FMA: 2x fp32 rate) ----------------
__device__ __forceinline__ ull pk2(float x, float y) {
    ull r; asm("mov.b64 %0, {%1, %2};" : "=l"(r) : "f"(x), "f"(y)); return r;
}
__device__ __forceinline__ void upk2(ull v, float& x, float& y) {
    asm("mov.b64 {%0, %1}, %2;" : "=f"(x), "=f"(y) : "l"(v));
}
__device__ __forceinline__ void fma2(ull& d, ull a, ull b) {
    asm("fma.rn.f32x2 %0, %1, %2, %0;" : "+l"(d) : "l"(a), "l"(b));
}

__device__ __forceinline__ float sigmoidf_(float x) {
    return __fdividef(1.0f, 1.0f + __expf(-x));
}

// ---------------- zero agg ----------------
__global__ void zero_agg_kernel(int n4) {
    float4 z = make_float4(0.f, 0.f, 0.f, 0.f);
    float4* p = reinterpret_cast<float4*>(G_AGG);
    for (int i = blockIdx.x * blockDim.x + threadIdx.x; i < n4; i += gridDim.x * blockDim.x)
        p[i] = z;
}

// ---------------- tiny precompute: rel_proj, qr_proj ----------------
// grid = R + B blocks, 64 threads each
__global__ void precompute_kernel(const float* __restrict__ rel_emb,
                                  const float* __restrict__ Wr,
                                  const float* __restrict__ Wqr,
                                  const float* __restrict__ b_qr,
                                  const int* __restrict__ q_rel,
                                  int R_, int B_) {
    __shared__ float srow[128];
    int b = blockIdx.x;
    int t = threadIdx.x;  // 0..63
    bool isrel = (b < R_);
    int row = isrel ? b : q_rel[b - R_];
    srow[t]      = rel_emb[row * 128 + t];
    srow[t + 64] = rel_emb[row * 128 + t + 64];
    __syncthreads();
    const float* Wp = isrel ? Wr : Wqr;
    float acc = isrel ? 0.f : b_qr[t];
    const float* w = Wp + t * 128;
#pragma unroll 8
    for (int k = 0; k < 128; k++) acc += srow[k] * w[k];
    if (isrel) g_relproj[b * 64 + t] = acc;
    else       g_qrproj[(b - R_) * 64 + t] = acc;
}

// ---------------- GEMM: C[rows,OC] = act(A[rows,128] @ W[OC,128]^T + bias) -------
// 256 threads, 64 rows/block, 64-col chunks, f32x2 inner loop.
// STREAM_OUT: use streaming (evict-first) stores for single-use outputs.
template <int OC, bool RELU, bool BIAS, bool STREAM_OUT>
__global__ __launch_bounds__(256) void gemm128_nt(const float* __restrict__ A,
                                                  const float* __restrict__ W,
                                                  const float* __restrict__ bias,
                                                  float* __restrict__ C,
                                                  int rows) {
    __shared__ float sA[128 * 68];   // [k][n], padded row = 68 floats
    __shared__ float sEp[32 * 68];   // epilogue staging (half tile)
    const int tid = threadIdx.x;
    const int row0 = blockIdx.x * 64;

    // load + transpose A tile: [64 rows][128 k] -> sA[k][n]
    for (int i = tid; i < 64 * 32; i += 256) {
        int n = i >> 5, k4 = (i & 31) << 2;
        float4 v = *reinterpret_cast<const float4*>(A + (size_t)(row0 + n) * 128 + k4);
        sA[(k4 + 0) * 68 + n] = v.x;
        sA[(k4 + 1) * 68 + n] = v.y;
        sA[(k4 + 2) * 68 + n] = v.z;
        sA[(k4 + 3) * 68 + n] = v.w;
    }
    __syncthreads();

    const int tr = tid & 15;   // 16 row groups of 4 rows
    const int tc = tid >> 4;   // 16 col groups of 4 cols

    for (int c0 = 0; c0 < OC; c0 += 64) {
        ull acc[2][4];
#pragma unroll
        for (int i = 0; i < 2; i++)
#pragma unroll
            for (int j = 0; j < 4; j++) acc[i][j] = 0ULL;

        const float* wb0 = W + (size_t)(c0 + tc * 4 + 0) * 128;
        const float* wb1 = W + (size_t)(c0 + tc * 4 + 1) * 128;
        const float* wb2 = W + (size_t)(c0 + tc * 4 + 2) * 128;
        const float* wb3 = W + (size_t)(c0 + tc * 4 + 3) * 128;

        for (int kb = 0; kb < 128; kb += 4) {
            float4 w0v = *reinterpret_cast<const float4*>(wb0 + kb);
            float4 w1v = *reinterpret_cast<const float4*>(wb1 + kb);
            float4 w2v = *reinterpret_cast<const float4*>(wb2 + kb);
            float4 w3v = *reinterpret_cast<const float4*>(wb3 + kb);
            const float w0a[4] = {w0v.x, w0v.y, w0v.z, w0v.w};
            const float w1a[4] = {w1v.x, w1v.y, w1v.z, w1v.w};
            const float w2a[4] = {w2v.x, w2v.y, w2v.z, w2v.w};
            const float w3a[4] = {w3v.x, w3v.y, w3v.z, w3v.w};
#pragma unroll
            for (int j = 0; j < 4; j++) {
                int k = kb + j;
                const float* ap = sA + k * 68 + (tr << 2);
                ull a0 = *reinterpret_cast<const ull*>(ap);
                ull a1 = *reinterpret_cast<const ull*>(ap + 2);
                ull d0 = pk2(w0a[j], w0a[j]);
                ull d1 = pk2(w1a[j], w1a[j]);
                ull d2 = pk2(w2a[j], w2a[j]);
                ull d3 = pk2(w3a[j], w3a[j]);
                fma2(acc[0][0], a0, d0); fma2(acc[1][0], a1, d0);
                fma2(acc[0][1], a0, d1); fma2(acc[1][1], a1, d1);
                fma2(acc[0][2], a0, d2); fma2(acc[1][2], a1, d2);
                fma2(acc[0][3], a0, d3); fma2(acc[1][3], a1, d3);
            }
        }

        // epilogue via smem for coalesced float4 stores (two 32-row passes)
        float bv[4];
#pragma unroll
        for (int j = 0; j < 4; j++) bv[j] = BIAS ? bias[c0 + tc * 4 + j] : 0.f;

        __syncthreads();
#pragma unroll
        for (int pass = 0; pass < 2; pass++) {
            if ((tr >> 3) == pass) {
#pragma unroll
                for (int rp = 0; rp < 2; rp++) {
#pragma unroll
                    for (int j = 0; j < 4; j++) {
                        float lo, hi;
                        upk2(acc[rp][j], lo, hi);
                        lo += bv[j]; hi += bv[j];
                        if (RELU) { lo = fmaxf(lo, 0.f); hi = fmaxf(hi, 0.f); }
                        int rl = (tr & 7) * 4 + rp * 2;
                        sEp[(rl + 0) * 68 + tc * 4 + j] = lo;
                        sEp[(rl + 1) * 68 + tc * 4 + j] = hi;
                    }
                }
            }
            __syncthreads();
            for (int i = tid; i < 32 * 16; i += 256) {
                int n = i >> 4, c4 = (i & 15) << 2;
                float4 v = *reinterpret_cast<const float4*>(sEp + n * 68 + c4);
                float4* dst = reinterpret_cast<float4*>(C + (size_t)(row0 + pass * 32 + n) * OC + c0 + c4);
                if (STREAM_OUT) __stcg(dst, v);
                else            *dst = v;
            }
            __syncthreads();
        }
    }
}

// ---------------- edge kernel: attention + scatter (one warp per edge) -------
__global__ __launch_bounds__(256) void edge_kernel(const float* __restrict__ hidden,
                                                   const float* __restrict__ rel_emb,
                                                   const float* __restrict__ w_alpha,
                                                   const float* __restrict__ b_alpha,
                                                   const int* __restrict__ sub,
                                                   const int* __restrict__ rel,
                                                   const int* __restrict__ obj,
                                                   const int* __restrict__ ebat,
                                                   int E_) {
    int lane = threadIdx.x & 31;
    int warp0 = (blockIdx.x * blockDim.x + threadIdx.x) >> 5;
    int wstep = (gridDim.x * blockDim.x) >> 5;
    float wa0 = __ldg(w_alpha + lane);
    float wa1 = __ldg(w_alpha + lane + 32);
    float ba  = __ldg(b_alpha);

    for (int e = warp0; e < E_; e += wstep) {
        int s  = __ldg(sub + e);
        int r  = __ldg(rel + e);
        int o  = __ldg(obj + e);
        int bq = __ldg(ebat + e);

        const float* hp = g_hs_proj + (size_t)s * 64;
        const float* rp = g_relproj + r * 64;
        const float* qp = g_qrproj + bq * 64;
        float t0 = hp[lane] + rp[lane] + qp[lane];
        float t1 = hp[lane + 32] + rp[lane + 32] + qp[lane + 32];
        t0 = fmaxf(t0, 0.f) * wa0;
        t1 = fmaxf(t1, 0.f) * wa1;
        float p = t0 + t1;
#pragma unroll
        for (int off = 16; off; off >>= 1) p += __shfl_xor_sync(0xffffffffu, p, off);
        float alpha = sigmoidf_(p + ba);

        float4 h  = *reinterpret_cast<const float4*>(hidden  + (size_t)s * 128 + lane * 4);
        float4 rr = *reinterpret_cast<const float4*>(rel_emb + (size_t)r * 128 + lane * 4);
        float* ag = G_AGG + (size_t)o * 128 + lane * 4;
        atomicAdd(ag + 0, alpha * (h.x + rr.x));
        atomicAdd(ag + 1, alpha * (h.y + rr.y));
        atomicAdd(ag + 2, alpha * (h.z + rr.z));
        atomicAdd(ag + 3, alpha * (h.w + rr.w));
    }
}

// ---------------- gate + score (one warp per node) ----------------
// gh = h0 @ W_hh^T + b_hh is computed exactly; if h0 row is all-zero the
// GEMM row is skipped (data-dependent, deterministic) and gh == b_hh.
__global__ __launch_bounds__(256) void gate_kernel(const float* __restrict__ h0,
                                                   const float* __restrict__ W_hh,
                                                   const float* __restrict__ b_hh,
                                                   const float* __restrict__ W_final,
                                                   float* __restrict__ scores,
                                                   int N_) {
    __shared__ float sh0[8][128];
    int warp = (blockIdx.x * 256 + threadIdx.x) >> 5;
    int wloc = threadIdx.x >> 5;
    int lane = threadIdx.x & 31;
    if (warp >= N_) return;

    const float* gin = G_GI + (size_t)warp * 384;
    int d = lane * 4;
    float4 ir  = __ldcs(reinterpret_cast<const float4*>(gin + d));
    float4 iz  = __ldcs(reinterpret_cast<const float4*>(gin + 128 + d));
    float4 inn = __ldcs(reinterpret_cast<const float4*>(gin + 256 + d));
    float4 h0v = *reinterpret_cast<const float4*>(h0 + (size_t)warp * 128 + d);

    bool zz = (h0v.x == 0.f) && (h0v.y == 0.f) && (h0v.z == 0.f) && (h0v.w == 0.f);
    unsigned m = __ballot_sync(0xffffffffu, zz);

    float hr[4], hz[4], hn[4];
    if (m == 0xffffffffu) {
        float4 t;
        t = *reinterpret_cast<const float4*>(b_hh + d);       hr[0] = t.x; hr[1] = t.y; hr[2] = t.z; hr[3] = t.w;
        t = *reinterpret_cast<const float4*>(b_hh + 128 + d); hz[0] = t.x; hz[1] = t.y; hz[2] = t.z; hz[3] = t.w;
        t = *reinterpret_cast<const float4*>(b_hh + 256 + d); hn[0] = t.x; hn[1] = t.y; hn[2] = t.z; hn[3] = t.w;
    } else {
        *reinterpret_cast<float4*>(&sh0[wloc][d]) = h0v;
        __syncwarp();
#pragma unroll
        for (int g = 0; g < 3; g++) {
#pragma unroll
            for (int j = 0; j < 4; j++) {
                int col = g * 128 + d + j;
                float acc = b_hh[col];
                const float* wrow = W_hh + (size_t)col * 128;
#pragma unroll 8
                for (int k = 0; k < 128; k++) acc += sh0[wloc][k] * wrow[k];
                if (g == 0) hr[j] = acc; else if (g == 1) hz[j] = acc; else hn[j] = acc;
            }
        }
    }

    float ira[4] = {ir.x, ir.y, ir.z, ir.w};
    float iza[4] = {iz.x, iz.y, iz.z, iz.w};
    float ina[4] = {inn.x, inn.y, inn.z, inn.w};
    float h0a[4] = {h0v.x, h0v.y, h0v.z, h0v.w};
    float4 wf = *reinterpret_cast<const float4*>(W_final + d);
    float wfa[4] = {wf.x, wf.y, wf.z, wf.w};

    float sc = 0.f;
#pragma unroll
    for (int j = 0; j < 4; j++) {
        float rg = sigmoidf_(ira[j] + hr[j]);
        float zg = sigmoidf_(iza[j] + hz[j]);
        float ng = tanhf(ina[j] + rg * hn[j]);
        float ho = (1.f - zg) * ng + zg * h0a[j];
        sc += ho * wfa[j];
    }
#pragma unroll
    for (int off = 16; off; off >>= 1) sc += __shfl_xor_sync(0xffffffffu, sc, off);
    if (lane == 0) scores[warp] = sc;
}

// ---------------- launch ----------------
extern "C" void kernel_launch(void* const* d_in, const int* in_sizes, int n_in,
                              void* d_out, int out_size) {
    const float* hidden  = (const float*)d_in[0];
    const float* rel_emb = (const float*)d_in[1];
    const float* Ws      = (const float*)d_in[2];
    const float* Wr      = (const float*)d_in[3];
    const float* Wqr     = (const float*)d_in[4];
    const float* b_qr    = (const float*)d_in[5];
    const float* w_alpha = (const float*)d_in[6];
    const float* b_alpha = (const float*)d_in[7];
    const float* W_h     = (const float*)d_in[8];
    const float* W_ih    = (const float*)d_in[9];
    const float* W_hh    = (const float*)d_in[10];
    const float* b_ih    = (const float*)d_in[11];
    const float* b_hh    = (const float*)d_in[12];
    const float* W_final = (const float*)d_in[13];
    const float* h0      = (const float*)d_in[14];
    const int*   sub     = (const int*)d_in[15];
    const int*   rel     = (const int*)d_in[16];
    const int*   obj     = (const int*)d_in[17];
    const int*   ebat    = (const int*)d_in[18];
    const int*   q_rel   = (const int*)d_in[19];

    const int N_ = in_sizes[0] / 128;   // 200000
    const int R_ = in_sizes[1] / 128;   // 67
    const int E_ = in_sizes[16];        // 500000
    const int B_ = in_sizes[19];        // 256

    float* scores = (float*)d_out;

    float* d_agg  = nullptr;
    float* d_hnew = nullptr;
    float* d_gi   = nullptr;
    cudaGetSymbolAddress((void**)&d_agg, g_pool);
    d_hnew = d_agg + (size_t)NMAX * 384;
    d_gi   = d_agg;

    // 1) zero agg
    zero_agg_kernel<<<2048, 256>>>(N_ * 32);  // N*128/4 float4s

    // 2) tiny projections: rel_proj, qr_proj(+b_qr)
    precompute_kernel<<<R_ + B_, 64>>>(rel_emb, Wr, Wqr, b_qr, q_rel, R_, B_);

    // 3) hs_proj = hidden @ Ws^T   [N,64]
    float* d_hsproj = nullptr;
    cudaGetSymbolAddress((void**)&d_hsproj, g_hs_proj);
    gemm128_nt<64, false, false, false><<<N_ / 64, 256>>>(hidden, Ws, nullptr, d_hsproj, N_);

    // 4) edge attention + message scatter (grid-stride, 8 warps/block)
    edge_kernel<<<4096, 256>>>(hidden, rel_emb, w_alpha, b_alpha,
                               sub, rel, obj, ebat, E_);

    // 5) h_new = relu(agg @ W_h^T)   [N,128]   (agg -> hnew, disjoint pool ranges)
    gemm128_nt<128, true, false, false><<<N_ / 64, 256>>>(d_agg, W_h, nullptr, d_hnew, N_);

    // 6) gi = h_new @ W_ih^T + b_ih  [N,384]   (hnew -> gi, agg range now dead)
    gemm128_nt<384, false, true, true><<<N_ / 64, 256>>>(d_hnew, W_ih, b_ih, d_gi, N_);

    // 7) GRU gate + final score
    gate_kernel<<<(N_ * 32 + 255) / 256, 256>>>(h0, W_hh, b_hh, W_final, scores, N_);
}

// round 6
// speedup vs baseline: 1.5737x; 1.5737x over previous
#include <cuda_runtime.h>
#include <cuda_bf16.h>
#include <cstdint>
#include <cstring>

typedef unsigned long long ull;

// ---------------- problem constants ----------------
#define NMAX 200000
#define DDIM 128
#define ADIM 64
#define RMAX 80
#define BMAX 256

// ---------------- device scratch ----------------
// pool: agg = [0,128N) ; hnew = [384N,512N) ; gi = [0,384N) (agg dead by then)
__device__ float g_pool[(size_t)NMAX * 512];
__device__ float g_hs_proj[NMAX * ADIM];
__device__ float g_relproj[RMAX * ADIM];
__device__ float g_qrproj[BMAX * ADIM];
// bf16 hi/lo weight images, plain row-major [rows][128]:
//  Ws hi@0, lo@16384 ; W_h hi@32768, lo@65536 ; W_ih hi@98304, lo@196608
__device__ __align__(16) unsigned char g_wp[294912];

// ---------------- helpers ----------------
__device__ __forceinline__ float sigmoidf_(float x) {
    return __fdividef(1.0f, 1.0f + __expf(-x));
}
__device__ __forceinline__ uint32_t smem_u32(const void* p) {
    uint32_t a;
    asm("{ .reg .u64 t; cvta.to.shared.u64 t, %1; cvt.u32.u64 %0, t; }" : "=r"(a) : "l"(p));
    return a;
}
__device__ __forceinline__ unsigned short bf_bits(__nv_bfloat16 h) {
    unsigned short s; memcpy(&s, &h, 2); return s;
}

#define LDSM4(r0, r1, r2, r3, addr) \
    asm volatile("ldmatrix.sync.aligned.m8n8.x4.shared.b16 {%0,%1,%2,%3}, [%4];" \
                 : "=r"(r0), "=r"(r1), "=r"(r2), "=r"(r3) : "r"(addr))

#define MMA16816(c, a, b) \
    asm volatile("mma.sync.aligned.m16n8k16.row.col.f32.bf16.bf16.f32 " \
                 "{%0,%1,%2,%3}, {%4,%5,%6,%7}, {%8,%9}, {%0,%1,%2,%3};" \
                 : "+f"((c)[0]), "+f"((c)[1]), "+f"((c)[2]), "+f"((c)[3]) \
                 : "r"((a)[0]), "r"((a)[1]), "r"((a)[2]), "r"((a)[3]), \
                   "r"((b)[0]), "r"((b)[1]))

// ---------------- zero agg ----------------
__global__ void zero_agg_kernel(int n4) {
    float4 z = make_float4(0.f, 0.f, 0.f, 0.f);
    float4* p = reinterpret_cast<float4*>(g_pool);
    for (int i = blockIdx.x * blockDim.x + threadIdx.x; i < n4; i += gridDim.x * blockDim.x)
        p[i] = z;
}

// ---------------- weight prep: fp32 -> bf16 hi/lo row-major images ----------------
__global__ void wprep_kernel(const float* __restrict__ Ws,
                             const float* __restrict__ Wh,
                             const float* __restrict__ Wih) {
    int i = blockIdx.x * blockDim.x + threadIdx.x;
    if (i >= 576 * 128) return;
    int row = i >> 7, k = i & 127;
    const float* src; int lrow; size_t hio, loo;
    if (row < 64)       { src = Ws;  lrow = row;       hio = 0;      loo = 16384; }
    else if (row < 192) { src = Wh;  lrow = row - 64;  hio = 32768;  loo = 65536; }
    else                { src = Wih; lrow = row - 192; hio = 98304;  loo = 196608; }
    float v = src[(size_t)lrow * 128 + k];
    __nv_bfloat16 hb = __float2bfloat16(v);
    float rem = v - __bfloat162float(hb);
    __nv_bfloat16 lb = __float2bfloat16(rem);
    reinterpret_cast<unsigned short*>(g_wp + hio)[(size_t)lrow * 128 + k] = bf_bits(hb);
    reinterpret_cast<unsigned short*>(g_wp + loo)[(size_t)lrow * 128 + k] = bf_bits(lb);
}

// ---------------- tiny precompute: rel_proj, qr_proj ----------------
__global__ void precompute_kernel(const float* __restrict__ rel_emb,
                                  const float* __restrict__ Wr,
                                  const float* __restrict__ Wqr,
                                  const float* __restrict__ b_qr,
                                  const int* __restrict__ q_rel,
                                  int R_, int B_) {
    __shared__ float srow[128];
    int b = blockIdx.x;
    int t = threadIdx.x;
    bool isrel = (b < R_);
    int row = isrel ? b : q_rel[b - R_];
    srow[t]      = rel_emb[row * 128 + t];
    srow[t + 64] = rel_emb[row * 128 + t + 64];
    __syncthreads();
    const float* Wp = isrel ? Wr : Wqr;
    float acc = isrel ? 0.f : b_qr[t];
    const float* w = Wp + t * 128;
#pragma unroll 8
    for (int k = 0; k < 128; k++) acc += srow[k] * w[k];
    if (isrel) g_relproj[b * 64 + t] = acc;
    else       g_qrproj[(b - R_) * 64 + t] = acc;
}

// ---------------- HMMA GEMM: C[rows,OC] = act(A[rows,128] @ W[OC,128]^T (+bias)) ----
// bf16 3-term split (a_hi*b_hi + a_lo*b_hi + a_hi*b_lo), fp32 register accumulators.
// CTA: 128 rows x CW cols per chunk, 8 warps as 4(m) x 2(n).
// EPI 0: plain store. EPI 1: relu store. EPI 2: +bias store.
template<int OC, int EPI>
__global__ __launch_bounds__(256) void gemm_mma(
    const float* __restrict__ A,
    const __nv_bfloat16* __restrict__ Whi,
    const __nv_bfloat16* __restrict__ Wlo,
    int rows, float* __restrict__ C, const float* __restrict__ bias)
{
    constexpr int CW  = (OC < 128) ? OC : 128;   // chunk width (cols)
    constexpr int NCH = OC / CW;                 // chunks
    constexpr int WN  = CW / 2;                  // per-warp n width
    constexpr int NT  = WN / 8;                  // n-tiles per warp

    extern __shared__ __align__(16) char smem[];
    // layout (bytes): A_hi [128][136]bf16 @0 (34816) ; A_lo @34816 ;
    //                 W_hi [CW][136] @69632 ; W_lo @69632+CW*272
    const uint32_t sb = smem_u32(smem);
    const uint32_t aHiU = sb, aLoU = sb + 34816;
    const uint32_t wHiU = sb + 69632, wLoU = sb + 69632 + CW * 272;

    const int tid = threadIdx.x, wid = tid >> 5, lane = tid & 31;
    const int row0 = blockIdx.x * 128;
    const int m0 = (wid & 3) * 32;
    const int n0 = (wid >> 2) * WN;

    // ---- stage A tile: fp32 -> bf16 hi/lo, padded rows (136 elems) ----
    for (int i = tid; i < 128 * 32; i += 256) {
        int r = i >> 5, k4 = (i & 31) << 2;
        float4 v = make_float4(0.f, 0.f, 0.f, 0.f);
        if (row0 + r < rows)
            v = *reinterpret_cast<const float4*>(A + (size_t)(row0 + r) * 128 + k4);
        float vv[4] = {v.x, v.y, v.z, v.w};
        unsigned short h[4], l[4];
#pragma unroll
        for (int q = 0; q < 4; q++) {
            __nv_bfloat16 hb = __float2bfloat16(vv[q]);
            float rem = vv[q] - __bfloat162float(hb);
            h[q] = bf_bits(hb);
            l[q] = bf_bits(__float2bfloat16(rem));
        }
        ull ph = (ull)h[0] | ((ull)h[1] << 16) | ((ull)h[2] << 32) | ((ull)h[3] << 48);
        ull pl = (ull)l[0] | ((ull)l[1] << 16) | ((ull)l[2] << 32) | ((ull)l[3] << 48);
        size_t off = (size_t)r * 272 + (size_t)k4 * 2;
        *reinterpret_cast<ull*>(smem + off)         = ph;
        *reinterpret_cast<ull*>(smem + 34816 + off) = pl;
    }

    for (int c = 0; c < NCH; c++) {
        __syncthreads();  // A staged / previous chunk fully consumed
        // ---- stage W chunk (hi+lo), 16B vectors, padded rows ----
        {
            const uint4* ghi = reinterpret_cast<const uint4*>(Whi + (size_t)c * CW * 128);
            const uint4* glo = reinterpret_cast<const uint4*>(Wlo + (size_t)c * CW * 128);
            for (int i = tid; i < CW * 16; i += 256) {   // CW rows x 16 uint4/row
                int r = i >> 4, v8 = i & 15;
                size_t doffb = (size_t)r * 272 + (size_t)v8 * 16;
                *reinterpret_cast<uint4*>(smem + 69632 + doffb)            = ghi[(size_t)r * 16 + v8];
                *reinterpret_cast<uint4*>(smem + 69632 + CW * 272 + doffb) = glo[(size_t)r * 16 + v8];
            }
        }
        __syncthreads();

        float acc[2][NT][4];
#pragma unroll
        for (int mi = 0; mi < 2; mi++)
#pragma unroll
            for (int nt = 0; nt < NT; nt++)
#pragma unroll
                for (int q = 0; q < 4; q++) acc[mi][nt][q] = 0.f;

        const int ar = lane & 15, ac = (lane >> 4) << 3;
        const int bg = lane >> 3;
        const int brr = ((bg >> 1) << 3) + (lane & 7);
        const int bcc = (bg & 1) << 3;

#pragma unroll
        for (int pass = 0; pass < 3; pass++) {
            const uint32_t aU = (pass == 1) ? aLoU : aHiU;
            const uint32_t bU = (pass == 2) ? wLoU : wHiU;
#pragma unroll
            for (int ks = 0; ks < 8; ks++) {
                const int k0 = ks * 16;
                uint32_t a0[4], a1[4];
                LDSM4(a0[0], a0[1], a0[2], a0[3],
                      aU + (uint32_t)((m0 + ar) * 272 + (k0 + ac) * 2));
                LDSM4(a1[0], a1[1], a1[2], a1[3],
                      aU + (uint32_t)((m0 + 16 + ar) * 272 + (k0 + ac) * 2));
                uint32_t b[NT][2];
#pragma unroll
                for (int nt2 = 0; nt2 < NT / 2; nt2++) {
                    uint32_t r0, r1, r2, r3;
                    LDSM4(r0, r1, r2, r3,
                          bU + (uint32_t)((n0 + nt2 * 16 + brr) * 272 + (k0 + bcc) * 2));
                    b[2 * nt2][0] = r0; b[2 * nt2][1] = r1;
                    b[2 * nt2 + 1][0] = r2; b[2 * nt2 + 1][1] = r3;
                }
#pragma unroll
                for (int nt = 0; nt < NT; nt++) {
                    MMA16816(acc[0][nt], a0, b[nt]);
                    MMA16816(acc[1][nt], a1, b[nt]);
                }
            }
        }

        // ---- epilogue: direct float2 stores ----
        const int rl = lane >> 2, cp = (lane & 3) * 2;
#pragma unroll
        for (int mi = 0; mi < 2; mi++) {
#pragma unroll
            for (int nt = 0; nt < NT; nt++) {
                int gcol = c * CW + n0 + nt * 8 + cp;
                float v0 = acc[mi][nt][0], v1 = acc[mi][nt][1];
                float v2 = acc[mi][nt][2], v3 = acc[mi][nt][3];
                if (EPI == 1) {
                    v0 = fmaxf(v0, 0.f); v1 = fmaxf(v1, 0.f);
                    v2 = fmaxf(v2, 0.f); v3 = fmaxf(v3, 0.f);
                } else if (EPI == 2) {
                    float b0 = __ldg(bias + gcol), b1 = __ldg(bias + gcol + 1);
                    v0 += b0; v1 += b1; v2 += b0; v3 += b1;
                }
                int grow = row0 + m0 + mi * 16 + rl;
                if (grow < rows)
                    *reinterpret_cast<float2*>(C + (size_t)grow * OC + gcol) = make_float2(v0, v1);
                if (grow + 8 < rows)
                    *reinterpret_cast<float2*>(C + (size_t)(grow + 8) * OC + gcol) = make_float2(v2, v3);
            }
        }
    }
}

// ---------------- edge kernel: attention + scatter (one warp per edge) ----------------
__global__ __launch_bounds__(256) void edge_kernel(const float* __restrict__ hidden,
                                                   const float* __restrict__ rel_emb,
                                                   const float* __restrict__ w_alpha,
                                                   const float* __restrict__ b_alpha,
                                                   const int* __restrict__ sub,
                                                   const int* __restrict__ rel,
                                                   const int* __restrict__ obj,
                                                   const int* __restrict__ ebat,
                                                   int E_) {
    int lane = threadIdx.x & 31;
    int warp0 = (blockIdx.x * blockDim.x + threadIdx.x) >> 5;
    int wstep = (gridDim.x * blockDim.x) >> 5;
    float wa0 = __ldg(w_alpha + lane);
    float wa1 = __ldg(w_alpha + lane + 32);
    float ba  = __ldg(b_alpha);

    for (int e = warp0; e < E_; e += wstep) {
        int s  = __ldg(sub + e);
        int r  = __ldg(rel + e);
        int o  = __ldg(obj + e);
        int bq = __ldg(ebat + e);

        const float* hp = g_hs_proj + (size_t)s * 64;
        const float* rp = g_relproj + r * 64;
        const float* qp = g_qrproj + bq * 64;
        float t0 = hp[lane] + rp[lane] + qp[lane];
        float t1 = hp[lane + 32] + rp[lane + 32] + qp[lane + 32];
        t0 = fmaxf(t0, 0.f) * wa0;
        t1 = fmaxf(t1, 0.f) * wa1;
        float p = t0 + t1;
#pragma unroll
        for (int off = 16; off; off >>= 1) p += __shfl_xor_sync(0xffffffffu, p, off);
        float alpha = sigmoidf_(p + ba);

        float4 h  = *reinterpret_cast<const float4*>(hidden  + (size_t)s * 128 + lane * 4);
        float4 rr = *reinterpret_cast<const float4*>(rel_emb + (size_t)r * 128 + lane * 4);
        float* ag = g_pool + (size_t)o * 128 + lane * 4;
        atomicAdd(ag + 0, alpha * (h.x + rr.x));
        atomicAdd(ag + 1, alpha * (h.y + rr.y));
        atomicAdd(ag + 2, alpha * (h.z + rr.z));
        atomicAdd(ag + 3, alpha * (h.w + rr.w));
    }
}

// ---------------- gate + score (one warp per node) ----------------
__global__ __launch_bounds__(256) void gate_kernel(const float* __restrict__ gi,
                                                   const float* __restrict__ h0,
                                                   const float* __restrict__ W_hh,
                                                   const float* __restrict__ b_hh,
                                                   const float* __restrict__ W_final,
                                                   float* __restrict__ scores,
                                                   int N_) {
    __shared__ float sh0[8][128];
    int warp = (blockIdx.x * 256 + threadIdx.x) >> 5;
    int wloc = threadIdx.x >> 5;
    int lane = threadIdx.x & 31;
    if (warp >= N_) return;

    const float* gin = gi + (size_t)warp * 384;
    int d = lane * 4;
    float4 ir  = __ldcs(reinterpret_cast<const float4*>(gin + d));
    float4 iz  = __ldcs(reinterpret_cast<const float4*>(gin + 128 + d));
    float4 inn = __ldcs(reinterpret_cast<const float4*>(gin + 256 + d));
    float4 h0v = *reinterpret_cast<const float4*>(h0 + (size_t)warp * 128 + d);

    bool zz = (h0v.x == 0.f) && (h0v.y == 0.f) && (h0v.z == 0.f) && (h0v.w == 0.f);
    unsigned m = __ballot_sync(0xffffffffu, zz);

    float hr[4], hz[4], hn[4];
    if (m == 0xffffffffu) {
        float4 t;
        t = *reinterpret_cast<const float4*>(b_hh + d);       hr[0] = t.x; hr[1] = t.y; hr[2] = t.z; hr[3] = t.w;
        t = *reinterpret_cast<const float4*>(b_hh + 128 + d); hz[0] = t.x; hz[1] = t.y; hz[2] = t.z; hz[3] = t.w;
        t = *reinterpret_cast<const float4*>(b_hh + 256 + d); hn[0] = t.x; hn[1] = t.y; hn[2] = t.z; hn[3] = t.w;
    } else {
        *reinterpret_cast<float4*>(&sh0[wloc][d]) = h0v;
        __syncwarp();
#pragma unroll
        for (int g = 0; g < 3; g++) {
#pragma unroll
            for (int j = 0; j < 4; j++) {
                int col = g * 128 + d + j;
                float acc = b_hh[col];
                const float* wrow = W_hh + (size_t)col * 128;
#pragma unroll 8
                for (int k = 0; k < 128; k++) acc += sh0[wloc][k] * wrow[k];
                if (g == 0) hr[j] = acc; else if (g == 1) hz[j] = acc; else hn[j] = acc;
            }
        }
    }

    float ira[4] = {ir.x, ir.y, ir.z, ir.w};
    float iza[4] = {iz.x, iz.y, iz.z, iz.w};
    float ina[4] = {inn.x, inn.y, inn.z, inn.w};
    float h0a[4] = {h0v.x, h0v.y, h0v.z, h0v.w};
    float4 wf = *reinterpret_cast<const float4*>(W_final + d);
    float wfa[4] = {wf.x, wf.y, wf.z, wf.w};

    float sc = 0.f;
#pragma unroll
    for (int j = 0; j < 4; j++) {
        float rg = sigmoidf_(ira[j] + hr[j]);
        float zg = sigmoidf_(iza[j] + hz[j]);
        float ng = tanhf(ina[j] + rg * hn[j]);
        float ho = (1.f - zg) * ng + zg * h0a[j];
        sc += ho * wfa[j];
    }
#pragma unroll
    for (int off = 16; off; off >>= 1) sc += __shfl_xor_sync(0xffffffffu, sc, off);
    if (lane == 0) scores[warp] = sc;
}

// ---------------- launch ----------------
extern "C" void kernel_launch(void* const* d_in, const int* in_sizes, int n_in,
                              void* d_out, int out_size) {
    const float* hidden  = (const float*)d_in[0];
    const float* rel_emb = (const float*)d_in[1];
    const float* Ws      = (const float*)d_in[2];
    const float* Wr      = (const float*)d_in[3];
    const float* Wqr     = (const float*)d_in[4];
    const float* b_qr    = (const float*)d_in[5];
    const float* w_alpha = (const float*)d_in[6];
    const float* b_alpha = (const float*)d_in[7];
    const float* W_h     = (const float*)d_in[8];
    const float* W_ih    = (const float*)d_in[9];
    const float* W_hh    = (const float*)d_in[10];
    const float* b_ih    = (const float*)d_in[11];
    const float* b_hh    = (const float*)d_in[12];
    const float* W_final = (const float*)d_in[13];
    const float* h0      = (const float*)d_in[14];
    const int*   sub     = (const int*)d_in[15];
    const int*   rel     = (const int*)d_in[16];
    const int*   obj     = (const int*)d_in[17];
    const int*   ebat    = (const int*)d_in[18];
    const int*   q_rel   = (const int*)d_in[19];

    const int N_ = in_sizes[0] / 128;
    const int R_ = in_sizes[1] / 128;
    const int E_ = in_sizes[16];
    const int B_ = in_sizes[19];

    float* scores = (float*)d_out;

    float* d_pool = nullptr; float* d_hsproj = nullptr; unsigned char* d_wp = nullptr;
    cudaGetSymbolAddress((void**)&d_pool, g_pool);
    cudaGetSymbolAddress((void**)&d_hsproj, g_hs_proj);
    cudaGetSymbolAddress((void**)&d_wp, g_wp);
    float* d_agg  = d_pool;                        // [0, 128N)
    float* d_hnew = d_pool + (size_t)NMAX * 384;   // [384N, 512N)
    float* d_gi   = d_pool;                        // [0, 384N), agg dead

    const int tiles = (N_ + 127) / 128;
    const int SH64  = 69632 + 64 * 272 * 2;    // 104448
    const int SH128 = 69632 + 128 * 272 * 2;   // 139264
    cudaFuncSetAttribute(gemm_mma<64, 0>,  cudaFuncAttributeMaxDynamicSharedMemorySize, SH64);
    cudaFuncSetAttribute(gemm_mma<128, 1>, cudaFuncAttributeMaxDynamicSharedMemorySize, SH128);
    cudaFuncSetAttribute(gemm_mma<384, 2>, cudaFuncAttributeMaxDynamicSharedMemorySize, SH128);

    // 1) zero agg
    zero_agg_kernel<<<2048, 256>>>(N_ * 32);

    // 2) weight prep (bf16 hi/lo row-major images)
    wprep_kernel<<<(576 * 128 + 255) / 256, 256>>>(Ws, W_h, W_ih);

    // 3) tiny projections
    precompute_kernel<<<R_ + B_, 64>>>(rel_emb, Wr, Wqr, b_qr, q_rel, R_, B_);

    // 4) hs_proj = hidden @ Ws^T  [N,64]  (HMMA)
    gemm_mma<64, 0><<<tiles, 256, SH64>>>(
        hidden,
        (const __nv_bfloat16*)(d_wp + 0), (const __nv_bfloat16*)(d_wp + 16384),
        N_, d_hsproj, nullptr);

    // 5) edge attention + message scatter
    edge_kernel<<<4096, 256>>>(hidden, rel_emb, w_alpha, b_alpha,
                               sub, rel, obj, ebat, E_);

    // 6) h_new = relu(agg @ W_h^T)  [N,128]  (HMMA)
    gemm_mma<128, 1><<<tiles, 256, SH128>>>(
        d_agg,
        (const __nv_bfloat16*)(d_wp + 32768), (const __nv_bfloat16*)(d_wp + 65536),
        N_, d_hnew, nullptr);

    // 7) gi = h_new @ W_ih^T + b_ih  [N,384]  (HMMA)
    gemm_mma<384, 2><<<tiles, 256, SH128>>>(
        d_hnew,
        (const __nv_bfloat16*)(d_wp + 98304), (const __nv_bfloat16*)(d_wp + 196608),
        N_, d_gi, b_ih);

    // 8) GRU gate + final score
    gate_kernel<<<(N_ * 32 + 255) / 256, 256>>>(d_gi, h0, W_hh, b_hh, W_final, scores, N_);
}

// round 7
// speedup vs baseline: 1.5741x; 1.0002x over previous
#include <cuda_runtime.h>
#include <cuda_bf16.h>
#include <cstdint>
#include <cstring>

typedef unsigned long long ull;

// ---------------- problem constants ----------------
#define NMAX 200000
#define DDIM 128
#define ADIM 64
#define RMAX 80
#define BMAX 256

// ---------------- device scratch ----------------
// pool: agg = [0,128N) ; hnew = [384N,512N) ; gi = [0,384N) (agg dead by then)
__device__ float g_pool[(size_t)NMAX * 512];
__device__ float g_hs_proj[NMAX * ADIM];
__device__ float g_relproj[RMAX * ADIM];
__device__ float g_qrproj[BMAX * ADIM];
// bf16 hi/lo weight images, plain row-major [rows][128]:
//  Ws hi@0, lo@16384 ; W_h hi@32768, lo@65536 ; W_ih hi@98304, lo@196608
__device__ __align__(16) unsigned char g_wp[294912];

// ---------------- helpers ----------------
__device__ __forceinline__ float sigmoidf_(float x) {
    return __fdividef(1.0f, 1.0f + __expf(-x));
}
__device__ __forceinline__ uint32_t smem_u32(const void* p) {
    uint32_t a;
    asm("{ .reg .u64 t; cvta.to.shared.u64 t, %1; cvt.u32.u64 %0, t; }" : "=r"(a) : "l"(p));
    return a;
}
__device__ __forceinline__ unsigned short bf_bits(__nv_bfloat16 h) {
    unsigned short s; memcpy(&s, &h, 2); return s;
}

#define LDSM4(r0, r1, r2, r3, addr) \
    asm volatile("ldmatrix.sync.aligned.m8n8.x4.shared.b16 {%0,%1,%2,%3}, [%4];" \
                 : "=r"(r0), "=r"(r1), "=r"(r2), "=r"(r3) : "r"(addr))

#define MMA16816(c, a, b) \
    asm volatile("mma.sync.aligned.m16n8k16.row.col.f32.bf16.bf16.f32 " \
                 "{%0,%1,%2,%3}, {%4,%5,%6,%7}, {%8,%9}, {%0,%1,%2,%3};" \
                 : "+f"((c)[0]), "+f"((c)[1]), "+f"((c)[2]), "+f"((c)[3]) \
                 : "r"((a)[0]), "r"((a)[1]), "r"((a)[2]), "r"((a)[3]), \
                   "r"((b)[0]), "r"((b)[1]))

// ---------------- zero agg ----------------
__global__ void zero_agg_kernel(int n4) {
    float4 z = make_float4(0.f, 0.f, 0.f, 0.f);
    float4* p = reinterpret_cast<float4*>(g_pool);
    for (int i = blockIdx.x * blockDim.x + threadIdx.x; i < n4; i += gridDim.x * blockDim.x)
        p[i] = z;
}

// ---------------- weight prep: fp32 -> bf16 hi/lo row-major images ----------------
__global__ void wprep_kernel(const float* __restrict__ Ws,
                             const float* __restrict__ Wh,
                             const float* __restrict__ Wih) {
    int i = blockIdx.x * blockDim.x + threadIdx.x;
    if (i >= 576 * 128) return;
    int row = i >> 7, k = i & 127;
    const float* src; int lrow; size_t hio, loo;
    if (row < 64)       { src = Ws;  lrow = row;       hio = 0;      loo = 16384; }
    else if (row < 192) { src = Wh;  lrow = row - 64;  hio = 32768;  loo = 65536; }
    else                { src = Wih; lrow = row - 192; hio = 98304;  loo = 196608; }
    float v = src[(size_t)lrow * 128 + k];
    __nv_bfloat16 hb = __float2bfloat16(v);
    float rem = v - __bfloat162float(hb);
    __nv_bfloat16 lb = __float2bfloat16(rem);
    reinterpret_cast<unsigned short*>(g_wp + hio)[(size_t)lrow * 128 + k] = bf_bits(hb);
    reinterpret_cast<unsigned short*>(g_wp + loo)[(size_t)lrow * 128 + k] = bf_bits(lb);
}

// ---------------- tiny precompute: rel_proj, qr_proj ----------------
__global__ void precompute_kernel(const float* __restrict__ rel_emb,
                                  const float* __restrict__ Wr,
                                  const float* __restrict__ Wqr,
                                  const float* __restrict__ b_qr,
                                  const int* __restrict__ q_rel,
                                  int R_, int B_) {
    __shared__ float srow[128];
    int b = blockIdx.x;
    int t = threadIdx.x;
    bool isrel = (b < R_);
    int row = isrel ? b : q_rel[b - R_];
    srow[t]      = rel_emb[row * 128 + t];
    srow[t + 64] = rel_emb[row * 128 + t + 64];
    __syncthreads();
    const float* Wp = isrel ? Wr : Wqr;
    float acc = isrel ? 0.f : b_qr[t];
    const float* w = Wp + t * 128;
#pragma unroll 8
    for (int k = 0; k < 128; k++) acc += srow[k] * w[k];
    if (isrel) g_relproj[b * 64 + t] = acc;
    else       g_qrproj[(b - R_) * 64 + t] = acc;
}

// ---------------- HMMA GEMM: C[rows,OC] = act(A[rows,128] @ W[OC,128]^T (+bias)) ----
// bf16 3-term split (a_hi*b_hi + a_lo*b_hi + a_hi*b_lo), fp32 register accumulators.
// CTA: 128 rows x CW cols per chunk, 8 warps as 4(m) x 2(n).
// EPI 0: plain store. EPI 1: relu store. EPI 2: +bias store.
template<int OC, int EPI>
__global__ __launch_bounds__(256) void gemm_mma(
    const float* __restrict__ A,
    const __nv_bfloat16* __restrict__ Whi,
    const __nv_bfloat16* __restrict__ Wlo,
    int rows, float* __restrict__ C, const float* __restrict__ bias)
{
    constexpr int CW  = (OC < 128) ? OC : 128;   // chunk width (cols)
    constexpr int NCH = OC / CW;                 // chunks
    constexpr int WN  = CW / 2;                  // per-warp n width
    constexpr int NT  = WN / 8;                  // n-tiles per warp

    extern __shared__ __align__(16) char smem[];
    // layout (bytes): A_hi [128][136]bf16 @0 (34816) ; A_lo @34816 ;
    //                 W_hi [CW][136] @69632 ; W_lo @69632+CW*272
    const uint32_t sb = smem_u32(smem);
    const uint32_t aHiU = sb, aLoU = sb + 34816;
    const uint32_t wHiU = sb + 69632, wLoU = sb + 69632 + CW * 272;

    const int tid = threadIdx.x, wid = tid >> 5, lane = tid & 31;
    const int row0 = blockIdx.x * 128;
    const int m0 = (wid & 3) * 32;
    const int n0 = (wid >> 2) * WN;

    // ---- stage A tile: fp32 -> bf16 hi/lo, padded rows (136 elems) ----
    for (int i = tid; i < 128 * 32; i += 256) {
        int r = i >> 5, k4 = (i & 31) << 2;
        float4 v = make_float4(0.f, 0.f, 0.f, 0.f);
        if (row0 + r < rows)
            v = *reinterpret_cast<const float4*>(A + (size_t)(row0 + r) * 128 + k4);
        float vv[4] = {v.x, v.y, v.z, v.w};
        unsigned short h[4], l[4];
#pragma unroll
        for (int q = 0; q < 4; q++) {
            __nv_bfloat16 hb = __float2bfloat16(vv[q]);
            float rem = vv[q] - __bfloat162float(hb);
            h[q] = bf_bits(hb);
            l[q] = bf_bits(__float2bfloat16(rem));
        }
        ull ph = (ull)h[0] | ((ull)h[1] << 16) | ((ull)h[2] << 32) | ((ull)h[3] << 48);
        ull pl = (ull)l[0] | ((ull)l[1] << 16) | ((ull)l[2] << 32) | ((ull)l[3] << 48);
        size_t off = (size_t)r * 272 + (size_t)k4 * 2;
        *reinterpret_cast<ull*>(smem + off)         = ph;
        *reinterpret_cast<ull*>(smem + 34816 + off) = pl;
    }

    for (int c = 0; c < NCH; c++) {
        __syncthreads();  // A staged / previous chunk fully consumed
        // ---- stage W chunk (hi+lo), 16B vectors, padded rows ----
        {
            const uint4* ghi = reinterpret_cast<const uint4*>(Whi + (size_t)c * CW * 128);
            const uint4* glo = reinterpret_cast<const uint4*>(Wlo + (size_t)c * CW * 128);
            for (int i = tid; i < CW * 16; i += 256) {   // CW rows x 16 uint4/row
                int r = i >> 4, v8 = i & 15;
                size_t doffb = (size_t)r * 272 + (size_t)v8 * 16;
                *reinterpret_cast<uint4*>(smem + 69632 + doffb)            = ghi[(size_t)r * 16 + v8];
                *reinterpret_cast<uint4*>(smem + 69632 + CW * 272 + doffb) = glo[(size_t)r * 16 + v8];
            }
        }
        __syncthreads();

        float acc[2][NT][4];
#pragma unroll
        for (int mi = 0; mi < 2; mi++)
#pragma unroll
            for (int nt = 0; nt < NT; nt++)
#pragma unroll
                for (int q = 0; q < 4; q++) acc[mi][nt][q] = 0.f;

        const int ar = lane & 15, ac = (lane >> 4) << 3;
        const int bg = lane >> 3;
        const int brr = ((bg >> 1) << 3) + (lane & 7);
        const int bcc = (bg & 1) << 3;

#pragma unroll
        for (int pass = 0; pass < 3; pass++) {
            const uint32_t aU = (pass == 1) ? aLoU : aHiU;
            const uint32_t bU = (pass == 2) ? wLoU : wHiU;
#pragma unroll
            for (int ks = 0; ks < 8; ks++) {
                const int k0 = ks * 16;
                uint32_t a0[4], a1[4];
                LDSM4(a0[0], a0[1], a0[2], a0[3],
                      aU + (uint32_t)((m0 + ar) * 272 + (k0 + ac) * 2));
                LDSM4(a1[0], a1[1], a1[2], a1[3],
                      aU + (uint32_t)((m0 + 16 + ar) * 272 + (k0 + ac) * 2));
                uint32_t b[NT][2];
#pragma unroll
                for (int nt2 = 0; nt2 < NT / 2; nt2++) {
                    uint32_t r0, r1, r2, r3;
                    LDSM4(r0, r1, r2, r3,
                          bU + (uint32_t)((n0 + nt2 * 16 + brr) * 272 + (k0 + bcc) * 2));
                    b[2 * nt2][0] = r0; b[2 * nt2][1] = r1;
                    b[2 * nt2 + 1][0] = r2; b[2 * nt2 + 1][1] = r3;
                }
#pragma unroll
                for (int nt = 0; nt < NT; nt++) {
                    MMA16816(acc[0][nt], a0, b[nt]);
                    MMA16816(acc[1][nt], a1, b[nt]);
                }
            }
        }

        // ---- epilogue: direct float2 stores ----
        const int rl = lane >> 2, cp = (lane & 3) * 2;
#pragma unroll
        for (int mi = 0; mi < 2; mi++) {
#pragma unroll
            for (int nt = 0; nt < NT; nt++) {
                int gcol = c * CW + n0 + nt * 8 + cp;
                float v0 = acc[mi][nt][0], v1 = acc[mi][nt][1];
                float v2 = acc[mi][nt][2], v3 = acc[mi][nt][3];
                if (EPI == 1) {
                    v0 = fmaxf(v0, 0.f); v1 = fmaxf(v1, 0.f);
                    v2 = fmaxf(v2, 0.f); v3 = fmaxf(v3, 0.f);
                } else if (EPI == 2) {
                    float b0 = __ldg(bias + gcol), b1 = __ldg(bias + gcol + 1);
                    v0 += b0; v1 += b1; v2 += b0; v3 += b1;
                }
                int grow = row0 + m0 + mi * 16 + rl;
                if (grow < rows)
                    *reinterpret_cast<float2*>(C + (size_t)grow * OC + gcol) = make_float2(v0, v1);
                if (grow + 8 < rows)
                    *reinterpret_cast<float2*>(C + (size_t)(grow + 8) * OC + gcol) = make_float2(v2, v3);
            }
        }
    }
}

// ---------------- edge kernel: attention + scatter (one warp per edge) ----------------
__global__ __launch_bounds__(256) void edge_kernel(const float* __restrict__ hidden,
                                                   const float* __restrict__ rel_emb,
                                                   const float* __restrict__ w_alpha,
                                                   const float* __restrict__ b_alpha,
                                                   const int* __restrict__ sub,
                                                   const int* __restrict__ rel,
                                                   const int* __restrict__ obj,
                                                   const int* __restrict__ ebat,
                                                   int E_) {
    int lane = threadIdx.x & 31;
    int warp0 = (blockIdx.x * blockDim.x + threadIdx.x) >> 5;
    int wstep = (gridDim.x * blockDim.x) >> 5;
    float wa0 = __ldg(w_alpha + lane);
    float wa1 = __ldg(w_alpha + lane + 32);
    float ba  = __ldg(b_alpha);

    for (int e = warp0; e < E_; e += wstep) {
        int s  = __ldg(sub + e);
        int r  = __ldg(rel + e);
        int o  = __ldg(obj + e);
        int bq = __ldg(ebat + e);

        const float* hp = g_hs_proj + (size_t)s * 64;
        const float* rp = g_relproj + r * 64;
        const float* qp = g_qrproj + bq * 64;
        float t0 = hp[lane] + rp[lane] + qp[lane];
        float t1 = hp[lane + 32] + rp[lane + 32] + qp[lane + 32];
        t0 = fmaxf(t0, 0.f) * wa0;
        t1 = fmaxf(t1, 0.f) * wa1;
        float p = t0 + t1;
#pragma unroll
        for (int off = 16; off; off >>= 1) p += __shfl_xor_sync(0xffffffffu, p, off);
        float alpha = sigmoidf_(p + ba);

        float4 h  = *reinterpret_cast<const float4*>(hidden  + (size_t)s * 128 + lane * 4);
        float4 rr = *reinterpret_cast<const float4*>(rel_emb + (size_t)r * 128 + lane * 4);
        float* ag = g_pool + (size_t)o * 128 + lane * 4;
        atomicAdd(ag + 0, alpha * (h.x + rr.x));
        atomicAdd(ag + 1, alpha * (h.y + rr.y));
        atomicAdd(ag + 2, alpha * (h.z + rr.z));
        atomicAdd(ag + 3, alpha * (h.w + rr.w));
    }
}

// ---------------- gate + score (one warp per node) ----------------
__global__ __launch_bounds__(256) void gate_kernel(const float* __restrict__ gi,
                                                   const float* __restrict__ h0,
                                                   const float* __restrict__ W_hh,
                                                   const float* __restrict__ b_hh,
                                                   const float* __restrict__ W_final,
                                                   float* __restrict__ scores,
                                                   int N_) {
    __shared__ float sh0[8][128];
    int warp = (blockIdx.x * 256 + threadIdx.x) >> 5;
    int wloc = threadIdx.x >> 5;
    int lane = threadIdx.x & 31;
    if (warp >= N_) return;

    const float* gin = gi + (size_t)warp * 384;
    int d = lane * 4;
    float4 ir  = __ldcs(reinterpret_cast<const float4*>(gin + d));
    float4 iz  = __ldcs(reinterpret_cast<const float4*>(gin + 128 + d));
    float4 inn = __ldcs(reinterpret_cast<const float4*>(gin + 256 + d));
    float4 h0v = *reinterpret_cast<const float4*>(h0 + (size_t)warp * 128 + d);

    bool zz = (h0v.x == 0.f) && (h0v.y == 0.f) && (h0v.z == 0.f) && (h0v.w == 0.f);
    unsigned m = __ballot_sync(0xffffffffu, zz);

    float hr[4], hz[4], hn[4];
    if (m == 0xffffffffu) {
        float4 t;
        t = *reinterpret_cast<const float4*>(b_hh + d);       hr[0] = t.x; hr[1] = t.y; hr[2] = t.z; hr[3] = t.w;
        t = *reinterpret_cast<const float4*>(b_hh + 128 + d); hz[0] = t.x; hz[1] = t.y; hz[2] = t.z; hz[3] = t.w;
        t = *reinterpret_cast<const float4*>(b_hh + 256 + d); hn[0] = t.x; hn[1] = t.y; hn[2] = t.z; hn[3] = t.w;
    } else {
        *reinterpret_cast<float4*>(&sh0[wloc][d]) = h0v;
        __syncwarp();
#pragma unroll
        for (int g = 0; g < 3; g++) {
#pragma unroll
            for (int j = 0; j < 4; j++) {
                int col = g * 128 + d + j;
                float acc = b_hh[col];
                const float* wrow = W_hh + (size_t)col * 128;
#pragma unroll 8
                for (int k = 0; k < 128; k++) acc += sh0[wloc][k] * wrow[k];
                if (g == 0) hr[j] = acc; else if (g == 1) hz[j] = acc; else hn[j] = acc;
            }
        }
    }

    float ira[4] = {ir.x, ir.y, ir.z, ir.w};
    float iza[4] = {iz.x, iz.y, iz.z, iz.w};
    float ina[4] = {inn.x, inn.y, inn.z, inn.w};
    float h0a[4] = {h0v.x, h0v.y, h0v.z, h0v.w};
    float4 wf = *reinterpret_cast<const float4*>(W_final + d);
    float wfa[4] = {wf.x, wf.y, wf.z, wf.w};

    float sc = 0.f;
#pragma unroll
    for (int j = 0; j < 4; j++) {
        float rg = sigmoidf_(ira[j] + hr[j]);
        float zg = sigmoidf_(iza[j] + hz[j]);
        float ng = tanhf(ina[j] + rg * hn[j]);
        float ho = (1.f - zg) * ng + zg * h0a[j];
        sc += ho * wfa[j];
    }
#pragma unroll
    for (int off = 16; off; off >>= 1) sc += __shfl_xor_sync(0xffffffffu, sc, off);
    if (lane == 0) scores[warp] = sc;
}

// ---------------- launch ----------------
extern "C" void kernel_launch(void* const* d_in, const int* in_sizes, int n_in,
                              void* d_out, int out_size) {
    const float* hidden  = (const float*)d_in[0];
    const float* rel_emb = (const float*)d_in[1];
    const float* Ws      = (const float*)d_in[2];
    const float* Wr      = (const float*)d_in[3];
    const float* Wqr     = (const float*)d_in[4];
    const float* b_qr    = (const float*)d_in[5];
    const float* w_alpha = (const float*)d_in[6];
    const float* b_alpha = (const float*)d_in[7];
    const float* W_h     = (const float*)d_in[8];
    const float* W_ih    = (const float*)d_in[9];
    const float* W_hh    = (const float*)d_in[10];
    const float* b_ih    = (const float*)d_in[11];
    const float* b_hh    = (const float*)d_in[12];
    const float* W_final = (const float*)d_in[13];
    const float* h0      = (const float*)d_in[14];
    const int*   sub     = (const int*)d_in[15];
    const int*   rel     = (const int*)d_in[16];
    const int*   obj     = (const int*)d_in[17];
    const int*   ebat    = (const int*)d_in[18];
    const int*   q_rel   = (const int*)d_in[19];

    const int N_ = in_sizes[0] / 128;
    const int R_ = in_sizes[1] / 128;
    const int E_ = in_sizes[16];
    const int B_ = in_sizes[19];

    float* scores = (float*)d_out;

    float* d_pool = nullptr; float* d_hsproj = nullptr; unsigned char* d_wp = nullptr;
    cudaGetSymbolAddress((void**)&d_pool, g_pool);
    cudaGetSymbolAddress((void**)&d_hsproj, g_hs_proj);
    cudaGetSymbolAddress((void**)&d_wp, g_wp);
    float* d_agg  = d_pool;                        // [0, 128N)
    float* d_hnew = d_pool + (size_t)NMAX * 384;   // [384N, 512N)
    float* d_gi   = d_pool;                        // [0, 384N), agg dead

    const int tiles = (N_ + 127) / 128;
    const int SH64  = 69632 + 64 * 272 * 2;    // 104448
    const int SH128 = 69632 + 128 * 272 * 2;   // 139264
    cudaFuncSetAttribute(gemm_mma<64, 0>,  cudaFuncAttributeMaxDynamicSharedMemorySize, SH64);
    cudaFuncSetAttribute(gemm_mma<128, 1>, cudaFuncAttributeMaxDynamicSharedMemorySize, SH128);
    cudaFuncSetAttribute(gemm_mma<384, 2>, cudaFuncAttributeMaxDynamicSharedMemorySize, SH128);

    // 1) zero agg
    zero_agg_kernel<<<2048, 256>>>(N_ * 32);

    // 2) weight prep (bf16 hi/lo row-major images)
    wprep_kernel<<<(576 * 128 + 255) / 256, 256>>>(Ws, W_h, W_ih);

    // 3) tiny projections
    precompute_kernel<<<R_ + B_, 64>>>(rel_emb, Wr, Wqr, b_qr, q_rel, R_, B_);

    // 4) hs_proj = hidden @ Ws^T  [N,64]  (HMMA)
    gemm_mma<64, 0><<<tiles, 256, SH64>>>(
        hidden,
        (const __nv_bfloat16*)(d_wp + 0), (const __nv_bfloat16*)(d_wp + 16384),
        N_, d_hsproj, nullptr);

    // 5) edge attention + message scatter
    edge_kernel<<<4096, 256>>>(hidden, rel_emb, w_alpha, b_alpha,
                               sub, rel, obj, ebat, E_);

    // 6) h_new = relu(agg @ W_h^T)  [N,128]  (HMMA)
    gemm_mma<128, 1><<<tiles, 256, SH128>>>(
        d_agg,
        (const __nv_bfloat16*)(d_wp + 32768), (const __nv_bfloat16*)(d_wp + 65536),
        N_, d_hnew, nullptr);

    // 7) gi = h_new @ W_ih^T + b_ih  [N,384]  (HMMA)
    gemm_mma<384, 2><<<tiles, 256, SH128>>>(
        d_hnew,
        (const __nv_bfloat16*)(d_wp + 98304), (const __nv_bfloat16*)(d_wp + 196608),
        N_, d_gi, b_ih);

    // 8) GRU gate + final score
    gate_kernel<<<(N_ * 32 + 255) / 256, 256>>>(d_gi, h0, W_hh, b_hh, W_final, scores, N_);
}

// round 8
// speedup vs baseline: 1.5747x; 1.0004x over previous
#include <cuda_runtime.h>
#include <cuda_bf16.h>
#include <cstdint>
#include <cstring>

typedef unsigned long long ull;

// ---------------- problem constants ----------------
#define NMAX 200000
#define DDIM 128
#define ADIM 64
#define RMAX 80
#define BMAX 256

// ---------------- device scratch ----------------
// pool: agg = [0,128N) ; hnew = [384N,512N) ; gi = [0,384N) (agg dead by then)
__device__ float g_pool[(size_t)NMAX * 512];
__device__ float g_hs_proj[NMAX * ADIM];
__device__ float g_relproj[RMAX * ADIM];
__device__ float g_qrproj[BMAX * ADIM];
// bf16 hi/lo weight images, plain row-major [rows][128]:
//  Ws hi@0, lo@16384 ; W_h hi@32768, lo@65536 ; W_ih hi@98304, lo@196608
__device__ __align__(16) unsigned char g_wp[294912];

// ---------------- helpers ----------------
__device__ __forceinline__ float sigmoidf_(float x) {
    return __fdividef(1.0f, 1.0f + __expf(-x));
}
__device__ __forceinline__ uint32_t smem_u32(const void* p) {
    uint32_t a;
    asm("{ .reg .u64 t; cvta.to.shared.u64 t, %1; cvt.u32.u64 %0, t; }" : "=r"(a) : "l"(p));
    return a;
}
__device__ __forceinline__ unsigned short bf_bits(__nv_bfloat16 h) {
    unsigned short s; memcpy(&s, &h, 2); return s;
}

#define LDSM4(r0, r1, r2, r3, addr) \
    asm volatile("ldmatrix.sync.aligned.m8n8.x4.shared.b16 {%0,%1,%2,%3}, [%4];" \
                 : "=r"(r0), "=r"(r1), "=r"(r2), "=r"(r3) : "r"(addr))

#define MMA16816(c, a, b) \
    asm volatile("mma.sync.aligned.m16n8k16.row.col.f32.bf16.bf16.f32 " \
                 "{%0,%1,%2,%3}, {%4,%5,%6,%7}, {%8,%9}, {%0,%1,%2,%3};" \
                 : "+f"((c)[0]), "+f"((c)[1]), "+f"((c)[2]), "+f"((c)[3]) \
                 : "r"((a)[0]), "r"((a)[1]), "r"((a)[2]), "r"((a)[3]), \
                   "r"((b)[0]), "r"((b)[1]))

// ---------------- zero agg ----------------
__global__ void zero_agg_kernel(int n4) {
    float4 z = make_float4(0.f, 0.f, 0.f, 0.f);
    float4* p = reinterpret_cast<float4*>(g_pool);
    for (int i = blockIdx.x * blockDim.x + threadIdx.x; i < n4; i += gridDim.x * blockDim.x)
        p[i] = z;
}

// ---------------- weight prep: fp32 -> bf16 hi/lo row-major images ----------------
__global__ void wprep_kernel(const float* __restrict__ Ws,
                             const float* __restrict__ Wh,
                             const float* __restrict__ Wih) {
    int i = blockIdx.x * blockDim.x + threadIdx.x;
    if (i >= 576 * 128) return;
    int row = i >> 7, k = i & 127;
    const float* src; int lrow; size_t hio, loo;
    if (row < 64)       { src = Ws;  lrow = row;       hio = 0;      loo = 16384; }
    else if (row < 192) { src = Wh;  lrow = row - 64;  hio = 32768;  loo = 65536; }
    else                { src = Wih; lrow = row - 192; hio = 98304;  loo = 196608; }
    float v = src[(size_t)lrow * 128 + k];
    __nv_bfloat16 hb = __float2bfloat16(v);
    float rem = v - __bfloat162float(hb);
    __nv_bfloat16 lb = __float2bfloat16(rem);
    reinterpret_cast<unsigned short*>(g_wp + hio)[(size_t)lrow * 128 + k] = bf_bits(hb);
    reinterpret_cast<unsigned short*>(g_wp + loo)[(size_t)lrow * 128 + k] = bf_bits(lb);
}

// ---------------- tiny precompute: rel_proj, qr_proj ----------------
__global__ void precompute_kernel(const float* __restrict__ rel_emb,
                                  const float* __restrict__ Wr,
                                  const float* __restrict__ Wqr,
                                  const float* __restrict__ b_qr,
                                  const int* __restrict__ q_rel,
                                  int R_, int B_) {
    __shared__ float srow[128];
    int b = blockIdx.x;
    int t = threadIdx.x;
    bool isrel = (b < R_);
    int row = isrel ? b : q_rel[b - R_];
    srow[t]      = rel_emb[row * 128 + t];
    srow[t + 64] = rel_emb[row * 128 + t + 64];
    __syncthreads();
    const float* Wp = isrel ? Wr : Wqr;
    float acc = isrel ? 0.f : b_qr[t];
    const float* w = Wp + t * 128;
#pragma unroll 8
    for (int k = 0; k < 128; k++) acc += srow[k] * w[k];
    if (isrel) g_relproj[b * 64 + t] = acc;
    else       g_qrproj[(b - R_) * 64 + t] = acc;
}

// ---------------- HMMA GEMM: C[rows,OC] = act(A[rows,128] @ W[OC,128]^T (+bias)) ----
// bf16 3-term split (a_hi*b_hi + a_lo*b_hi + a_hi*b_lo), fp32 register accumulators.
// CTA: 128 rows x CW cols per chunk, 8 warps as 4(m) x 2(n).
// EPI 0: plain store. EPI 1: relu store. EPI 2: +bias store.
template<int OC, int EPI>
__global__ __launch_bounds__(256) void gemm_mma(
    const float* __restrict__ A,
    const __nv_bfloat16* __restrict__ Whi,
    const __nv_bfloat16* __restrict__ Wlo,
    int rows, float* __restrict__ C, const float* __restrict__ bias)
{
    constexpr int CW  = (OC < 128) ? OC : 128;   // chunk width (cols)
    constexpr int NCH = OC / CW;                 // chunks
    constexpr int WN  = CW / 2;                  // per-warp n width
    constexpr int NT  = WN / 8;                  // n-tiles per warp

    extern __shared__ __align__(16) char smem[];
    // layout (bytes): A_hi [128][136]bf16 @0 (34816) ; A_lo @34816 ;
    //                 W_hi [CW][136] @69632 ; W_lo @69632+CW*272
    const uint32_t sb = smem_u32(smem);
    const uint32_t aHiU = sb, aLoU = sb + 34816;
    const uint32_t wHiU = sb + 69632, wLoU = sb + 69632 + CW * 272;

    const int tid = threadIdx.x, wid = tid >> 5, lane = tid & 31;
    const int row0 = blockIdx.x * 128;
    const int m0 = (wid & 3) * 32;
    const int n0 = (wid >> 2) * WN;

    // ---- stage A tile: fp32 -> bf16 hi/lo, padded rows (136 elems) ----
    for (int i = tid; i < 128 * 32; i += 256) {
        int r = i >> 5, k4 = (i & 31) << 2;
        float4 v = make_float4(0.f, 0.f, 0.f, 0.f);
        if (row0 + r < rows)
            v = *reinterpret_cast<const float4*>(A + (size_t)(row0 + r) * 128 + k4);
        float vv[4] = {v.x, v.y, v.z, v.w};
        unsigned short h[4], l[4];
#pragma unroll
        for (int q = 0; q < 4; q++) {
            __nv_bfloat16 hb = __float2bfloat16(vv[q]);
            float rem = vv[q] - __bfloat162float(hb);
            h[q] = bf_bits(hb);
            l[q] = bf_bits(__float2bfloat16(rem));
        }
        ull ph = (ull)h[0] | ((ull)h[1] << 16) | ((ull)h[2] << 32) | ((ull)h[3] << 48);
        ull pl = (ull)l[0] | ((ull)l[1] << 16) | ((ull)l[2] << 32) | ((ull)l[3] << 48);
        size_t off = (size_t)r * 272 + (size_t)k4 * 2;
        *reinterpret_cast<ull*>(smem + off)         = ph;
        *reinterpret_cast<ull*>(smem + 34816 + off) = pl;
    }

    for (int c = 0; c < NCH; c++) {
        __syncthreads();  // A staged / previous chunk fully consumed
        // ---- stage W chunk (hi+lo), 16B vectors, padded rows ----
        {
            const uint4* ghi = reinterpret_cast<const uint4*>(Whi + (size_t)c * CW * 128);
            const uint4* glo = reinterpret_cast<const uint4*>(Wlo + (size_t)c * CW * 128);
            for (int i = tid; i < CW * 16; i += 256) {   // CW rows x 16 uint4/row
                int r = i >> 4, v8 = i & 15;
                size_t doffb = (size_t)r * 272 + (size_t)v8 * 16;
                *reinterpret_cast<uint4*>(smem + 69632 + doffb)            = ghi[(size_t)r * 16 + v8];
                *reinterpret_cast<uint4*>(smem + 69632 + CW * 272 + doffb) = glo[(size_t)r * 16 + v8];
            }
        }
        __syncthreads();

        float acc[2][NT][4];
#pragma unroll
        for (int mi = 0; mi < 2; mi++)
#pragma unroll
            for (int nt = 0; nt < NT; nt++)
#pragma unroll
                for (int q = 0; q < 4; q++) acc[mi][nt][q] = 0.f;

        const int ar = lane & 15, ac = (lane >> 4) << 3;
        const int bg = lane >> 3;
        const int brr = ((bg >> 1) << 3) + (lane & 7);
        const int bcc = (bg & 1) << 3;

#pragma unroll
        for (int pass = 0; pass < 3; pass++) {
            const uint32_t aU = (pass == 1) ? aLoU : aHiU;
            const uint32_t bU = (pass == 2) ? wLoU : wHiU;
#pragma unroll
            for (int ks = 0; ks < 8; ks++) {
                const int k0 = ks * 16;
                uint32_t a0[4], a1[4];
                LDSM4(a0[0], a0[1], a0[2], a0[3],
                      aU + (uint32_t)((m0 + ar) * 272 + (k0 + ac) * 2));
                LDSM4(a1[0], a1[1], a1[2], a1[3],
                      aU + (uint32_t)((m0 + 16 + ar) * 272 + (k0 + ac) * 2));
                uint32_t b[NT][2];
#pragma unroll
                for (int nt2 = 0; nt2 < NT / 2; nt2++) {
                    uint32_t r0, r1, r2, r3;
                    LDSM4(r0, r1, r2, r3,
                          bU + (uint32_t)((n0 + nt2 * 16 + brr) * 272 + (k0 + bcc) * 2));
                    b[2 * nt2][0] = r0; b[2 * nt2][1] = r1;
                    b[2 * nt2 + 1][0] = r2; b[2 * nt2 + 1][1] = r3;
                }
#pragma unroll
                for (int nt = 0; nt < NT; nt++) {
                    MMA16816(acc[0][nt], a0, b[nt]);
                    MMA16816(acc[1][nt], a1, b[nt]);
                }
            }
        }

        // ---- epilogue: direct float2 stores ----
        const int rl = lane >> 2, cp = (lane & 3) * 2;
#pragma unroll
        for (int mi = 0; mi < 2; mi++) {
#pragma unroll
            for (int nt = 0; nt < NT; nt++) {
                int gcol = c * CW + n0 + nt * 8 + cp;
                float v0 = acc[mi][nt][0], v1 = acc[mi][nt][1];
                float v2 = acc[mi][nt][2], v3 = acc[mi][nt][3];
                if (EPI == 1) {
                    v0 = fmaxf(v0, 0.f); v1 = fmaxf(v1, 0.f);
                    v2 = fmaxf(v2, 0.f); v3 = fmaxf(v3, 0.f);
                } else if (EPI == 2) {
                    float b0 = __ldg(bias + gcol), b1 = __ldg(bias + gcol + 1);
                    v0 += b0; v1 += b1; v2 += b0; v3 += b1;
                }
                int grow = row0 + m0 + mi * 16 + rl;
                if (grow < rows)
                    *reinterpret_cast<float2*>(C + (size_t)grow * OC + gcol) = make_float2(v0, v1);
                if (grow + 8 < rows)
                    *reinterpret_cast<float2*>(C + (size_t)(grow + 8) * OC + gcol) = make_float2(v2, v3);
            }
        }
    }
}

// ---------------- edge kernel: attention + scatter (one warp per edge) ----------------
__global__ __launch_bounds__(256) void edge_kernel(const float* __restrict__ hidden,
                                                   const float* __restrict__ rel_emb,
                                                   const float* __restrict__ w_alpha,
                                                   const float* __restrict__ b_alpha,
                                                   const int* __restrict__ sub,
                                                   const int* __restrict__ rel,
                                                   const int* __restrict__ obj,
                                                   const int* __restrict__ ebat,
                                                   int E_) {
    int lane = threadIdx.x & 31;
    int warp0 = (blockIdx.x * blockDim.x + threadIdx.x) >> 5;
    int wstep = (gridDim.x * blockDim.x) >> 5;
    float wa0 = __ldg(w_alpha + lane);
    float wa1 = __ldg(w_alpha + lane + 32);
    float ba  = __ldg(b_alpha);

    for (int e = warp0; e < E_; e += wstep) {
        int s  = __ldg(sub + e);
        int r  = __ldg(rel + e);
        int o  = __ldg(obj + e);
        int bq = __ldg(ebat + e);

        const float* hp = g_hs_proj + (size_t)s * 64;
        const float* rp = g_relproj + r * 64;
        const float* qp = g_qrproj + bq * 64;
        float t0 = hp[lane] + rp[lane] + qp[lane];
        float t1 = hp[lane + 32] + rp[lane + 32] + qp[lane + 32];
        t0 = fmaxf(t0, 0.f) * wa0;
        t1 = fmaxf(t1, 0.f) * wa1;
        float p = t0 + t1;
#pragma unroll
        for (int off = 16; off; off >>= 1) p += __shfl_xor_sync(0xffffffffu, p, off);
        float alpha = sigmoidf_(p + ba);

        float4 h  = *reinterpret_cast<const float4*>(hidden  + (size_t)s * 128 + lane * 4);
        float4 rr = *reinterpret_cast<const float4*>(rel_emb + (size_t)r * 128 + lane * 4);
        float* ag = g_pool + (size_t)o * 128 + lane * 4;
        atomicAdd(ag + 0, alpha * (h.x + rr.x));
        atomicAdd(ag + 1, alpha * (h.y + rr.y));
        atomicAdd(ag + 2, alpha * (h.z + rr.z));
        atomicAdd(ag + 3, alpha * (h.w + rr.w));
    }
}

// ---------------- gate + score (one warp per node) ----------------
__global__ __launch_bounds__(256) void gate_kernel(const float* __restrict__ gi,
                                                   const float* __restrict__ h0,
                                                   const float* __restrict__ W_hh,
                                                   const float* __restrict__ b_hh,
                                                   const float* __restrict__ W_final,
                                                   float* __restrict__ scores,
                                                   int N_) {
    __shared__ float sh0[8][128];
    int warp = (blockIdx.x * 256 + threadIdx.x) >> 5;
    int wloc = threadIdx.x >> 5;
    int lane = threadIdx.x & 31;
    if (warp >= N_) return;

    const float* gin = gi + (size_t)warp * 384;
    int d = lane * 4;
    float4 ir  = __ldcs(reinterpret_cast<const float4*>(gin + d));
    float4 iz  = __ldcs(reinterpret_cast<const float4*>(gin + 128 + d));
    float4 inn = __ldcs(reinterpret_cast<const float4*>(gin + 256 + d));
    float4 h0v = *reinterpret_cast<const float4*>(h0 + (size_t)warp * 128 + d);

    bool zz = (h0v.x == 0.f) && (h0v.y == 0.f) && (h0v.z == 0.f) && (h0v.w == 0.f);
    unsigned m = __ballot_sync(0xffffffffu, zz);

    float hr[4], hz[4], hn[4];
    if (m == 0xffffffffu) {
        float4 t;
        t = *reinterpret_cast<const float4*>(b_hh + d);       hr[0] = t.x; hr[1] = t.y; hr[2] = t.z; hr[3] = t.w;
        t = *reinterpret_cast<const float4*>(b_hh + 128 + d); hz[0] = t.x; hz[1] = t.y; hz[2] = t.z; hz[3] = t.w;
        t = *reinterpret_cast<const float4*>(b_hh + 256 + d); hn[0] = t.x; hn[1] = t.y; hn[2] = t.z; hn[3] = t.w;
    } else {
        *reinterpret_cast<float4*>(&sh0[wloc][d]) = h0v;
        __syncwarp();
#pragma unroll
        for (int g = 0; g < 3; g++) {
#pragma unroll
            for (int j = 0; j < 4; j++) {
                int col = g * 128 + d + j;
                float acc = b_hh[col];
                const float* wrow = W_hh + (size_t)col * 128;
#pragma unroll 8
                for (int k = 0; k < 128; k++) acc += sh0[wloc][k] * wrow[k];
                if (g == 0) hr[j] = acc; else if (g == 1) hz[j] = acc; else hn[j] = acc;
            }
        }
    }

    float ira[4] = {ir.x, ir.y, ir.z, ir.w};
    float iza[4] = {iz.x, iz.y, iz.z, iz.w};
    float ina[4] = {inn.x, inn.y, inn.z, inn.w};
    float h0a[4] = {h0v.x, h0v.y, h0v.z, h0v.w};
    float4 wf = *reinterpret_cast<const float4*>(W_final + d);
    float wfa[4] = {wf.x, wf.y, wf.z, wf.w};

    float sc = 0.f;
#pragma unroll
    for (int j = 0; j < 4; j++) {
        float rg = sigmoidf_(ira[j] + hr[j]);
        float zg = sigmoidf_(iza[j] + hz[j]);
        float ng = tanhf(ina[j] + rg * hn[j]);
        float ho = (1.f - zg) * ng + zg * h0a[j];
        sc += ho * wfa[j];
    }
#pragma unroll
    for (int off = 16; off; off >>= 1) sc += __shfl_xor_sync(0xffffffffu, sc, off);
    if (lane == 0) scores[warp] = sc;
}

// ---------------- launch ----------------
extern "C" void kernel_launch(void* const* d_in, const int* in_sizes, int n_in,
                              void* d_out, int out_size) {
    const float* hidden  = (const float*)d_in[0];
    const float* rel_emb = (const float*)d_in[1];
    const float* Ws      = (const float*)d_in[2];
    const float* Wr      = (const float*)d_in[3];
    const float* Wqr     = (const float*)d_in[4];
    const float* b_qr    = (const float*)d_in[5];
    const float* w_alpha = (const float*)d_in[6];
    const float* b_alpha = (const float*)d_in[7];
    const float* W_h     = (const float*)d_in[8];
    const float* W_ih    = (const float*)d_in[9];
    const float* W_hh    = (const float*)d_in[10];
    const float* b_ih    = (const float*)d_in[11];
    const float* b_hh    = (const float*)d_in[12];
    const float* W_final = (const float*)d_in[13];
    const float* h0      = (const float*)d_in[14];
    const int*   sub     = (const int*)d_in[15];
    const int*   rel     = (const int*)d_in[16];
    const int*   obj     = (const int*)d_in[17];
    const int*   ebat    = (const int*)d_in[18];
    const int*   q_rel   = (const int*)d_in[19];

    const int N_ = in_sizes[0] / 128;
    const int R_ = in_sizes[1] / 128;
    const int E_ = in_sizes[16];
    const int B_ = in_sizes[19];

    float* scores = (float*)d_out;

    float* d_pool = nullptr; float* d_hsproj = nullptr; unsigned char* d_wp = nullptr;
    cudaGetSymbolAddress((void**)&d_pool, g_pool);
    cudaGetSymbolAddress((void**)&d_hsproj, g_hs_proj);
    cudaGetSymbolAddress((void**)&d_wp, g_wp);
    float* d_agg  = d_pool;                        // [0, 128N)
    float* d_hnew = d_pool + (size_t)NMAX * 384;   // [384N, 512N)
    float* d_gi   = d_pool;                        // [0, 384N), agg dead

    const int tiles = (N_ + 127) / 128;
    const int SH64  = 69632 + 64 * 272 * 2;    // 104448
    const int SH128 = 69632 + 128 * 272 * 2;   // 139264
    cudaFuncSetAttribute(gemm_mma<64, 0>,  cudaFuncAttributeMaxDynamicSharedMemorySize, SH64);
    cudaFuncSetAttribute(gemm_mma<128, 1>, cudaFuncAttributeMaxDynamicSharedMemorySize, SH128);
    cudaFuncSetAttribute(gemm_mma<384, 2>, cudaFuncAttributeMaxDynamicSharedMemorySize, SH128);

    // 1) zero agg
    zero_agg_kernel<<<2048, 256>>>(N_ * 32);

    // 2) weight prep (bf16 hi/lo row-major images)
    wprep_kernel<<<(576 * 128 + 255) / 256, 256>>>(Ws, W_h, W_ih);

    // 3) tiny projections
    precompute_kernel<<<R_ + B_, 64>>>(rel_emb, Wr, Wqr, b_qr, q_rel, R_, B_);

    // 4) hs_proj = hidden @ Ws^T  [N,64]  (HMMA)
    gemm_mma<64, 0><<<tiles, 256, SH64>>>(
        hidden,
        (const __nv_bfloat16*)(d_wp + 0), (const __nv_bfloat16*)(d_wp + 16384),
        N_, d_hsproj, nullptr);

    // 5) edge attention + message scatter
    edge_kernel<<<4096, 256>>>(hidden, rel_emb, w_alpha, b_alpha,
                               sub, rel, obj, ebat, E_);

    // 6) h_new = relu(agg @ W_h^T)  [N,128]  (HMMA)
    gemm_mma<128, 1><<<tiles, 256, SH128>>>(
        d_agg,
        (const __nv_bfloat16*)(d_wp + 32768), (const __nv_bfloat16*)(d_wp + 65536),
        N_, d_hnew, nullptr);

    // 7) gi = h_new @ W_ih^T + b_ih  [N,384]  (HMMA)
    gemm_mma<384, 2><<<tiles, 256, SH128>>>(
        d_hnew,
        (const __nv_bfloat16*)(d_wp + 98304), (const __nv_bfloat16*)(d_wp + 196608),
        N_, d_gi, b_ih);

    // 8) GRU gate + final score
    gate_kernel<<<(N_ * 32 + 255) / 256, 256>>>(d_gi, h0, W_hh, b_hh, W_final, scores, N_);
}